// round 11
// baseline (speedup 1.0000x reference)
#include <cuda_runtime.h>

// E8 quantizer, closed form, f32x2 even/odd packing, 2 independent points
// per thread (non-persistent).
//
// Math (rounds 1-10): all 240 E8 roots have ||c||^2 = 2, so the softmax of
// -(dist^2)/T reduces to softmax(beta * x.c), beta = 2/0.3, and factorizes:
//  Type-1 (112 roots, +-1 at dims i,j):  A_i = 2cosh(beta x_i)
//     denom1 = sum_{i<j} A_i A_j,  num1_d = (a_d b_d) * exclSum_d(A)
//  Type-2 (128 roots, (+-1/2)^8, even parity): a_i = 2cosh(bx_i/2), b_i = 2sinh(bx_i/2)
//     denom2 = (prod a + prod b)/2, num2_d = (b_d exclProd_d(a) + a_d exclProd_d(b))/4
//  with A = a^2 - 2.  16 EX2 + 1 RCP per point.  All-positive adds /
//  sign-safe muls -> no cancellation; +- root pairs => denom >= 1.
//
// Packing: even dims in the lo lane, odd dims in the hi lane of f32x2
// (FFMA2) registers — packed pairs coincide with memory-adjacent float pairs,
// so pack/unpack costs zero MOVs (R10 win: ALU 0.8%).  Only three half-swaps
// (S, Pa, Pb) cross lanes.
//
// R10 diagnosis: stream is now short (~150 warp-instr/point) and issue fell
// to 37% — pure latency exposure (577-cyc naked LDG + MUFU chain).  Fix:
// two INDEPENDENT points per thread, all four LDG.128 front-batched, so each
// point's compute fills the other's stall holes.  CTA tiles 512 points;
// thread t takes base+t and base+t+256 — both streams stay warp-coalesced
// (R2 lesson).  Non-persistent grid (persistent shapes pay ~3us wall
// penalty: R4/R9 vs R1/R10).

#define BETA_HALF_LOG2E 4.8089834696568576f   // (2/0.3)/2 * log2(e)

typedef unsigned long long u64;
union F2 { float2 f; u64 u; };

__device__ __forceinline__ float ex2_approx(float x) {
    float y; asm("ex2.approx.ftz.f32 %0, %1;" : "=f"(y) : "f"(x)); return y;
}
__device__ __forceinline__ float rcp_approx(float x) {
    float y; asm("rcp.approx.ftz.f32 %0, %1;" : "=f"(y) : "f"(x)); return y;
}
__device__ __forceinline__ float2 f2fma(float2 a, float2 b, float2 c) {
    F2 A{a}, B{b}, C{c}, R;
    asm("fma.rn.f32x2 %0, %1, %2, %3;" : "=l"(R.u) : "l"(A.u), "l"(B.u), "l"(C.u));
    return R.f;
}
__device__ __forceinline__ float2 f2add(float2 a, float2 b) {
    F2 A{a}, B{b}, R;
    asm("add.rn.f32x2 %0, %1, %2;" : "=l"(R.u) : "l"(A.u), "l"(B.u));
    return R.f;
}
__device__ __forceinline__ float2 f2sub(float2 a, float2 b) {
    F2 A{a}, B{b}, R;
    asm("sub.rn.f32x2 %0, %1, %2;" : "=l"(R.u) : "l"(A.u), "l"(B.u));
    return R.f;
}
__device__ __forceinline__ float2 f2mul(float2 a, float2 b) {
    F2 A{a}, B{b}, R;
    asm("mul.rn.f32x2 %0, %1, %2;" : "=l"(R.u) : "l"(A.u), "l"(B.u));
    return R.f;
}
__device__ __forceinline__ float2 swap2(float2 v) { return make_float2(v.y, v.x); }

// one packed point: inputs are the two loaded float4's, outputs two float4's
__device__ __forceinline__ void e8_point(const float4& v0, const float4& v1,
                                         float4& r0, float4& r1)
{
    float2 X[4] = { make_float2(v0.x, v0.y), make_float2(v0.z, v0.w),
                    make_float2(v1.x, v1.y), make_float2(v1.z, v1.w) };

    const float2 cB  = make_float2( BETA_HALF_LOG2E,  BETA_HALF_LOG2E);
    const float2 cN2 = make_float2(-2.0f, -2.0f);

    float2 a[4], b[4], A[4];
#pragma unroll
    for (int i = 0; i < 4; i++) {
        float2 t = f2mul(X[i], cB);
        float2 hp = make_float2(ex2_approx( t.x), ex2_approx( t.y));
        float2 hn = make_float2(ex2_approx(-t.x), ex2_approx(-t.y));
        a[i] = f2add(hp, hn);               // 2cosh(beta x / 2)
        b[i] = f2sub(hp, hn);               // 2sinh(beta x / 2)
        A[i] = f2fma(a[i], a[i], cN2);      // 2cosh(beta x)
    }

    // per-half trees (lo lane = even dims, hi lane = odd dims)
    float2 s01 = f2add(A[0], A[1]), s23 = f2add(A[2], A[3]);
    float2 S = f2add(s01, s23);
    float2 eo[4] = { f2add(A[1], s23), f2add(A[0], s23),
                     f2add(s01, A[3]), f2add(s01, A[2]) };

    float2 sig = f2mul(A[2], A[3]);          // within-half pair sums (6 each)
    sig = f2fma(A[0], A[1], sig);
    sig = f2fma(s01, s23, sig);

    float2 pa01 = f2mul(a[0], a[1]), pa23 = f2mul(a[2], a[3]);
    float2 Pa = f2mul(pa01, pa23);
    float2 epa[4] = { f2mul(a[1], pa23), f2mul(a[0], pa23),
                      f2mul(pa01, a[3]), f2mul(pa01, a[2]) };

    float2 pb01 = f2mul(b[0], b[1]), pb23 = f2mul(b[2], b[3]);
    float2 Pb = f2mul(pb01, pb23);
    float2 epb[4] = { f2mul(b[1], pb23), f2mul(b[0], pb23),
                      f2mul(pb01, b[3]), f2mul(pb01, b[2]) };

    // scalar denominator, once per point
    float D1 = fmaf(S.x, S.y, sig.x + sig.y);        // all 28 pairs A_iA_j
    float D  = fmaf(0.5f, fmaf(Pa.x, Pa.y, Pb.x * Pb.y), D1);
    float rd = rcp_approx(D);
    float2 rD = make_float2(rd, rd);

    const float2 cQ = make_float2(0.25f, 0.25f);
    float2 Ssw = swap2(S);
    float2 PaQ = f2mul(swap2(Pa), cQ);
    float2 PbQ = f2mul(swap2(Pb), cQ);

    float2 o[4];
#pragma unroll
    for (int d = 0; d < 4; d++) {
        float2 eS    = f2add(eo[d], Ssw);            // exclSum_d(A)
        float2 ea    = f2mul(epa[d], PaQ);           // exclProd_d(a)/4
        float2 eb    = f2mul(epb[d], PbQ);           // exclProd_d(b)/4
        float2 inner = f2fma(b[d], ea, f2mul(a[d], eb));
        float2 num   = f2fma(f2mul(a[d], b[d]), eS, inner);
        o[d] = f2mul(num, rD);
    }

    r0 = make_float4(o[0].x, o[0].y, o[1].x, o[1].y);
    r1 = make_float4(o[2].x, o[2].y, o[3].x, o[3].y);
}

__global__ void __launch_bounds__(256) e8_quantize_kernel(
    const float4* __restrict__ x4, float4* __restrict__ o4, int n)
{
    int base = blockIdx.x * 512 + threadIdx.x;   // CTA tile = 512 points
    int pA = base;
    int pB = base + 256;
    bool hasA = pA < n;
    bool hasB = pB < n;

    // front-batch all four LDG.128 (two coalesced streams)
    float4 a0, a1, b0, b1;
    if (hasA) { a0 = x4[2 * pA + 0]; a1 = x4[2 * pA + 1]; }
    if (hasB) { b0 = x4[2 * pB + 0]; b1 = x4[2 * pB + 1]; }

    if (hasA) {
        float4 r0, r1;
        e8_point(a0, a1, r0, r1);
        o4[2 * pA + 0] = r0;
        o4[2 * pA + 1] = r1;
    }
    if (hasB) {
        float4 r0, r1;
        e8_point(b0, b1, r0, r1);
        o4[2 * pB + 0] = r0;
        o4[2 * pB + 1] = r1;
    }
}

extern "C" void kernel_launch(void* const* d_in, const int* in_sizes, int n_in,
                              void* d_out, int out_size) {
    const float4* x4 = (const float4*)d_in[0];   // [N, 8] fp32
    float4* o4 = (float4*)d_out;
    int n = in_sizes[0] / 8;
    const int block = 256;
    int grid = (n + 511) / 512;                  // 2 points per thread
    e8_quantize_kernel<<<grid, block>>>(x4, o4, n);
}